// round 11
// baseline (speedup 1.0000x reference)
#include <cuda_runtime.h>
#include <cuda_bf16.h>
#include <cstdint>

// LinearRationalSpline forward — persistent TMA pipeline + tree-structured
// compute (short dependency chains; latency-paced warps were the limiter).
// inputs:  [16384, 64] f32, params: [16384, 64, 63] f32, out: [2*N] f32
//
// Config = best observed (TILE=64, TPB=64, double-buffered 16.1 KB TMA
// stages, 6 blocks/SM, one wave over real SM count). This round replaces the
// serial softmax-cumsum chains (64 cyc) with Sklansky prefix trees (16 cyc)
// and the serial bin-search select chains (60 cyc) with fmax/fmin reduce
// trees (16 cyc). Register budget is free at this occupancy (170/thread).

#define TPB   64
#define TILE  64
#define NBINS 16
#define STAGES 2

#define STAGE_FLOATS (TILE * 63)                 // 4032
#define STAGE_BYTES  (STAGE_FLOATS * 4)          // 16128
#define BUF_OFF      64
#define SMEM_TOTAL   (BUF_OFF + STAGES * STAGE_BYTES)  // 32320

__device__ __forceinline__ uint32_t smem_u32(const void* p) {
    uint32_t a;
    asm("{ .reg .u64 t; cvta.to.shared.u64 t, %1; cvt.u32.u64 %0, t; }"
        : "=r"(a) : "l"(p));
    return a;
}
__device__ __forceinline__ void mbar_init(uint32_t mbar, uint32_t cnt) {
    asm volatile("mbarrier.init.shared.b64 [%0], %1;" :: "r"(mbar), "r"(cnt) : "memory");
}
__device__ __forceinline__ void mbar_expect_tx(uint32_t mbar, uint32_t bytes) {
    asm volatile("mbarrier.arrive.expect_tx.shared.b64 _, [%0], %1;"
                 :: "r"(mbar), "r"(bytes) : "memory");
}
__device__ __forceinline__ void mbar_wait(uint32_t mbar, uint32_t parity) {
    asm volatile(
        "{\n\t"
        ".reg .pred P1;\n\t"
        "WAIT_%=:\n\t"
        "mbarrier.try_wait.parity.acquire.cta.shared::cta.b64 P1, [%0], %1, 0x989680;\n\t"
        "@P1 bra.uni DONE_%=;\n\t"
        "bra.uni WAIT_%=;\n\t"
        "DONE_%=:\n\t"
        "}" :: "r"(mbar), "r"(parity) : "memory");
}
__device__ __forceinline__ void bulk_g2s(uint32_t dst, const void* src,
                                         uint32_t bytes, uint32_t mbar) {
    asm volatile(
        "cp.async.bulk.shared::cluster.global.mbarrier::complete_tx::bytes "
        "[%0], [%1], %2, [%3];"
        :: "r"(dst), "l"(src), "r"(bytes), "r"(mbar) : "memory");
}
__device__ __forceinline__ void fence_async() {
    asm volatile("fence.proxy.async.shared::cta;" ::: "memory");
}
__device__ __forceinline__ float rcp_approx(float x) {
    float r; asm("rcp.approx.f32 %0, %1;" : "=f"(r) : "f"(x)); return r;
}
__device__ __forceinline__ float sqrt_approx(float x) {
    float r; asm("sqrt.approx.f32 %0, %1;" : "=f"(r) : "f"(x)); return r;
}
__device__ __forceinline__ float softplus_f(float v) {
    return fmaxf(v, 0.0f) + __logf(1.0f + __expf(-fabsf(v)));
}

__device__ __forceinline__ void issue_tile(uint32_t sbase, int stg,
                                           const float* params, long long tile) {
    uint32_t mbar = sbase + stg * 8;
    uint32_t dst  = sbase + BUF_OFF + (uint32_t)stg * STAGE_BYTES;
    mbar_expect_tx(mbar, STAGE_BYTES);
    bulk_g2s(dst, params + tile * STAGE_FLOATS, STAGE_BYTES, mbar);
}

// Sklansky prefix sum over 16 registers: depth 4 (16 cyc), 32 FADDs.
#define PREFIX16(c) do {                                                     \
    c[1]+=c[0];  c[3]+=c[2];  c[5]+=c[4];   c[7]+=c[6];                      \
    c[9]+=c[8];  c[11]+=c[10];c[13]+=c[12]; c[15]+=c[14];                    \
    c[2]+=c[1];  c[3]+=c[1];  c[6]+=c[5];   c[7]+=c[5];                      \
    c[10]+=c[9]; c[11]+=c[9]; c[14]+=c[13]; c[15]+=c[13];                    \
    c[4]+=c[3];  c[5]+=c[3];  c[6]+=c[3];   c[7]+=c[3];                      \
    c[12]+=c[11];c[13]+=c[11];c[14]+=c[11]; c[15]+=c[11];                    \
    c[8]+=c[7];  c[9]+=c[7];  c[10]+=c[7];  c[11]+=c[7];                     \
    c[12]+=c[7]; c[13]+=c[7]; c[14]+=c[7];  c[15]+=c[7];                     \
} while (0)

// one element's spline math (p = 63 params in smem, stride-63 conflict-free)
__device__ __forceinline__ void spline_one(const float* __restrict__ p, float x,
                                           float& outv, float& lad) {
    constexpr float BOUND = 3.0f;
    constexpr float MBW   = 0.001f;
    constexpr float MBH   = 0.001f;
    constexpr float MIND  = 0.001f;
    constexpr float MINL  = 0.025f;
    constexpr float EPSV  = 1e-6f;

    // independent exps (MUFU-parallel), then tree prefix sums
    float cw[NBINS], ch[NBINS];
    #pragma unroll
    for (int i = 0; i < NBINS; i++) cw[i] = __expf(p[i]);
    #pragma unroll
    for (int i = 0; i < NBINS; i++) ch[i] = __expf(p[16 + i]);
    PREFIX16(cw);
    PREFIX16(ch);

    const float Aw = (6.0f * (1.0f - 16.0f * MBW)) * rcp_approx(cw[NBINS - 1]);
    const float Ah = (6.0f * (1.0f - 16.0f * MBH)) * rcp_approx(ch[NBINS - 1]);

    // knots (independent fmas)
    const float xm = x - EPSV;               // kv + eps <= x  <=>  kv <= xm
    float kv[15], hv[15];
    #pragma unroll
    for (int i = 1; i <= 15; i++) {
        kv[i - 1] = fmaf(Aw, cw[i - 1], 6.0f * MBW * (float)i - BOUND);
        hv[i - 1] = fmaf(Ah, ch[i - 1], 6.0f * MBH * (float)i - BOUND);
    }

    // selection trees. knots are increasing, selected set {kv<=xm} is a
    // prefix: knot_b = max selected, knot_{b+1} = min unselected.
    float csel[16], wsel[16], yasel[16], yksel[16];
    int   cnt16[16];
    #pragma unroll
    for (int i = 0; i < 15; i++) {
        const bool c = kv[i] <= xm;
        cnt16[i] = c ? 1 : 0;
        csel[i]  = c ? kv[i] : -BOUND;   // -> cumw  (max)
        wsel[i]  = c ? BOUND : kv[i];    // -> wnext (min)
        yasel[i] = c ? hv[i] : -BOUND;   // -> ya    (max)
        yksel[i] = c ? BOUND : hv[i];    // -> ykn   (min)
    }
    cnt16[15] = (BOUND <= xm) ? 1 : 0;
    csel[15]  = -BOUND;
    wsel[15]  =  BOUND;
    yasel[15] = -BOUND;
    yksel[15] =  BOUND;

    #pragma unroll
    for (int d = 8; d >= 1; d >>= 1) {
        #pragma unroll
        for (int i = 0; i < d; i++) {
            cnt16[i] += cnt16[i + d];
            csel[i]  = fmaxf(csel[i],  csel[i + d]);
            wsel[i]  = fminf(wsel[i],  wsel[i + d]);
            yasel[i] = fmaxf(yasel[i], yasel[i + d]);
            yksel[i] = fminf(yksel[i], yksel[i + d]);
        }
    }
    const int   b     = cnt16[0] > 15 ? 15 : cnt16[0];
    const float cumw  = csel[0];
    const float wnext = wsel[0];
    const float ya    = yasel[0];
    const float ykn   = yksel[0];

    const float input_widths  = wnext - cumw;
    const float input_heights = ykn - ya;
    const float yb = input_heights + ya;

    // derivatives + lambda (dynamic LDS; b is ready early via the int tree)
    const float d0r  = p[32 + (b > 0  ? b - 1 : 0)];
    const float d1r  = p[32 + (b < 15 ? b     : 14)];
    const float lraw = p[47 + b];

    const float d0 = (b == 0)  ? (1.0f - MIND) : (MIND + softplus_f(d0r));
    const float d1 = (b == 15) ? (1.0f - MIND) : (MIND + softplus_f(d1r));

    const float sig = rcp_approx(1.0f + __expf(-lraw));
    const float lam = fmaf(1.0f - 2.0f * MINL, sig, MINL);

    // rational spline
    const float wbv = sqrt_approx(__fdividef(d0, d1));
    const float lwb = lam * wbv;
    const float delta = __fdividef(input_heights, input_widths);
    const float wc = __fdividef(fmaf(lam, d0, (wbv - lwb) * d1), delta);
    const float l1 = 1.0f - lam;
    const float yc = __fdividef(lwb * yb + l1 * ya, l1 + lwb);

    const float theta = __fdividef(x - cumw, input_widths);
    const bool ind = theta <= lam;
    const float ltheta = lam - theta;

    const float wcyc = wc * yc;
    const float wcyctheta = wcyc * theta;
    const float num = ind ? fmaf(ya, ltheta, wcyctheta)
                          : (wcyc - wcyctheta) - (wbv * yb) * ltheta;
    const float wctheta = wc * theta;
    const float den = ind ? (wctheta + ltheta)
                          : (wc - wctheta) - wbv * ltheta;
    outv = __fdividef(num, den);

    // logabsdet = log( wc*sel / (w * den^2) )
    const float sel = ind ? lam * (yc - ya) : (wbv - lwb) * (yb - yc);
    lad = __logf(__fdividef(wc * sel, input_widths * (den * den)));
}

__global__ __launch_bounds__(TPB)
void lrs_kernel(const float* __restrict__ inputs,
                const float* __restrict__ params,
                float* __restrict__ out,
                int N, int numTiles)
{
    constexpr float BOUND = 3.0f;

    extern __shared__ char smem[];
    const uint32_t sbase = smem_u32(smem);
    const int tid = threadIdx.x;

    if (tid == 0) {
        mbar_init(sbase + 0, 1);
        mbar_init(sbase + 8, 1);
        fence_async();
    }
    __syncthreads();

    const long long step = gridDim.x;

    // prologue: prefetch both param stages + x two tiles ahead (LDG queue)
    if (tid == 0) {
        long long t0 = blockIdx.x;
        long long t1 = blockIdx.x + step;
        if (t0 < numTiles && (t0 + 1) * TILE <= N) issue_tile(sbase, 0, params, t0);
        if (t1 < numTiles && (t1 + 1) * TILE <= N) issue_tile(sbase, 1, params, t1);
    }
    float xq0 = 0.0f, xq1 = 0.0f;
    {
        long long t0 = blockIdx.x;
        long long t1 = blockIdx.x + step;
        if (t0 < numTiles) {
            long long i = t0 * TILE + tid; if (i >= N) i = N - 1;
            xq0 = __ldg(inputs + i);
        }
        if (t1 < numTiles) {
            long long i = t1 * TILE + tid; if (i >= N) i = N - 1;
            xq1 = __ldg(inputs + i);
        }
    }

    int ph0 = 0, ph1 = 0;
    int stg = 0;

    for (long long tile = blockIdx.x; tile < numTiles; tile += step) {
        const long long e0 = tile * TILE;
        const int elems = (N - e0) < TILE ? (int)(N - e0) : TILE;
        float* bufp = (float*)(smem + BUF_OFF + (size_t)stg * STAGE_BYTES);

        const float x = xq0;
        xq0 = xq1;
        {
            long long nt = tile + 2 * step;
            if (nt < numTiles) {
                long long i = nt * TILE + tid; if (i >= N) i = N - 1;
                xq1 = __ldg(inputs + i);
            }
        }

        if (elems == TILE) {
            if (stg == 0) { mbar_wait(sbase + 0, ph0); ph0 ^= 1; }
            else          { mbar_wait(sbase + 8, ph1); ph1 ^= 1; }
        } else {
            for (int i = tid; i < elems * 63; i += TPB)
                bufp[i] = params[e0 * 63 + i];
            __syncthreads();
        }

        if (tid < elems) {
            float outv, lad;
            spline_one(bufp + tid * 63, x, outv, lad);

            const bool outside = (x < -BOUND) || (x > BOUND);
            const int e = (int)e0 + tid;
            out[e]     = outside ? x    : outv;
            out[N + e] = outside ? 0.0f : lad;
        }

        __syncthreads();   // both warps done reading this stage

        long long nt = tile + (long long)STAGES * step;
        if (tid == 0 && nt < numTiles && (nt + 1) * TILE <= N) {
            fence_async();
            issue_tile(sbase, stg, params, nt);
        }
        stg ^= 1;
    }
}

extern "C" void kernel_launch(void* const* d_in, const int* in_sizes, int n_in,
                              void* d_out, int out_size) {
    const float* inputs = (const float*)d_in[0];
    const float* params = (const float*)d_in[1];
    float* out = (float*)d_out;
    const int N = in_sizes[0];
    const int numTiles = (N + TILE - 1) / TILE;

    cudaFuncSetAttribute(lrs_kernel,
                         cudaFuncAttributeMaxDynamicSharedMemorySize, SMEM_TOTAL);

    int dev = 0, nsm = 148;
    cudaGetDevice(&dev);
    cudaDeviceGetAttribute(&nsm, cudaDevAttrMultiProcessorCount, dev);
    int maxb = 1;
    cudaOccupancyMaxActiveBlocksPerMultiprocessor(&maxb, lrs_kernel, TPB, SMEM_TOTAL);
    if (maxb < 1) maxb = 1;

    long long grid = (long long)nsm * maxb;
    if (grid > numTiles) grid = numTiles;
    lrs_kernel<<<(int)grid, TPB, SMEM_TOTAL>>>(inputs, params, out, N, numTiles);
}

// round 12
// speedup vs baseline: 1.0359x; 1.0359x over previous
#include <cuda_runtime.h>
#include <cuda_bf16.h>
#include <cstdint>

// LinearRationalSpline forward — persistent TMA pipeline, 2 threads/element.
// inputs:  [16384, 64] f32, params: [16384, 64, 63] f32, out: [2*N] f32
//
// TILE=64 / TPB=128: adjacent lanes (2q, 2q+1) cooperate on element q.
// Each lane handles 8 of the 16 bins (half the exps / prefix / knots /
// selects), partials combined with warp shuffles (valid: knots monotone ->
// selected set is a prefix). Same 32.3 KB smem as the best prior config but
// 24 warps/SM instead of 12 -> compute stops pacing the TMA pipeline.

#define TPB   128
#define TILE  64
#define STAGES 2

#define STAGE_FLOATS (TILE * 63)                 // 4032
#define STAGE_BYTES  (STAGE_FLOATS * 4)          // 16128
#define BUF_OFF      64
#define SMEM_TOTAL   (BUF_OFF + STAGES * STAGE_BYTES)  // 32320

__device__ __forceinline__ uint32_t smem_u32(const void* p) {
    uint32_t a;
    asm("{ .reg .u64 t; cvta.to.shared.u64 t, %1; cvt.u32.u64 %0, t; }"
        : "=r"(a) : "l"(p));
    return a;
}
__device__ __forceinline__ void mbar_init(uint32_t mbar, uint32_t cnt) {
    asm volatile("mbarrier.init.shared.b64 [%0], %1;" :: "r"(mbar), "r"(cnt) : "memory");
}
__device__ __forceinline__ void mbar_expect_tx(uint32_t mbar, uint32_t bytes) {
    asm volatile("mbarrier.arrive.expect_tx.shared.b64 _, [%0], %1;"
                 :: "r"(mbar), "r"(bytes) : "memory");
}
__device__ __forceinline__ void mbar_wait(uint32_t mbar, uint32_t parity) {
    asm volatile(
        "{\n\t"
        ".reg .pred P1;\n\t"
        "WAIT_%=:\n\t"
        "mbarrier.try_wait.parity.acquire.cta.shared::cta.b64 P1, [%0], %1, 0x989680;\n\t"
        "@P1 bra.uni DONE_%=;\n\t"
        "bra.uni WAIT_%=;\n\t"
        "DONE_%=:\n\t"
        "}" :: "r"(mbar), "r"(parity) : "memory");
}
__device__ __forceinline__ void bulk_g2s(uint32_t dst, const void* src,
                                         uint32_t bytes, uint32_t mbar) {
    asm volatile(
        "cp.async.bulk.shared::cluster.global.mbarrier::complete_tx::bytes "
        "[%0], [%1], %2, [%3];"
        :: "r"(dst), "l"(src), "r"(bytes), "r"(mbar) : "memory");
}
__device__ __forceinline__ void fence_async() {
    asm volatile("fence.proxy.async.shared::cta;" ::: "memory");
}
__device__ __forceinline__ float rcp_approx(float x) {
    float r; asm("rcp.approx.f32 %0, %1;" : "=f"(r) : "f"(x)); return r;
}
__device__ __forceinline__ float sqrt_approx(float x) {
    float r; asm("sqrt.approx.f32 %0, %1;" : "=f"(r) : "f"(x)); return r;
}
__device__ __forceinline__ float softplus_f(float v) {
    return fmaxf(v, 0.0f) + __logf(1.0f + __expf(-fabsf(v)));
}

__device__ __forceinline__ void issue_tile(uint32_t sbase, int stg,
                                           const float* params, long long tile) {
    uint32_t mbar = sbase + stg * 8;
    uint32_t dst  = sbase + BUF_OFF + (uint32_t)stg * STAGE_BYTES;
    mbar_expect_tx(mbar, STAGE_BYTES);
    bulk_g2s(dst, params + tile * STAGE_FLOATS, STAGE_BYTES, mbar);
}

__global__ __launch_bounds__(TPB)
void lrs_kernel(const float* __restrict__ inputs,
                const float* __restrict__ params,
                float* __restrict__ out,
                int N, int numTiles)
{
    constexpr float BOUND = 3.0f;
    constexpr float MBW   = 0.001f;
    constexpr float MBH   = 0.001f;
    constexpr float MIND  = 0.001f;
    constexpr float MINL  = 0.025f;
    constexpr float EPSV  = 1e-6f;

    extern __shared__ char smem[];
    const uint32_t sbase = smem_u32(smem);
    const int tid  = threadIdx.x;
    const int q    = tid >> 1;          // element within tile (0..63)
    const int half = tid & 1;           // 0: bins 0-7, 1: bins 8-15
    const int boff = half << 3;

    if (tid == 0) {
        mbar_init(sbase + 0, 1);
        mbar_init(sbase + 8, 1);
        fence_async();
    }
    __syncthreads();

    const long long step = gridDim.x;

    if (tid == 0) {
        long long t0 = blockIdx.x;
        long long t1 = blockIdx.x + step;
        if (t0 < numTiles && (t0 + 1) * TILE <= N) issue_tile(sbase, 0, params, t0);
        if (t1 < numTiles && (t1 + 1) * TILE <= N) issue_tile(sbase, 1, params, t1);
    }
    float xq0 = 0.0f, xq1 = 0.0f;
    {
        long long t0 = blockIdx.x;
        long long t1 = blockIdx.x + step;
        if (t0 < numTiles) {
            long long i = t0 * TILE + q; if (i >= N) i = N - 1;
            xq0 = __ldg(inputs + i);
        }
        if (t1 < numTiles) {
            long long i = t1 * TILE + q; if (i >= N) i = N - 1;
            xq1 = __ldg(inputs + i);
        }
    }

    int ph0 = 0, ph1 = 0;
    int stg = 0;

    for (long long tile = blockIdx.x; tile < numTiles; tile += step) {
        const long long e0 = tile * TILE;
        const int elems = (N - e0) < TILE ? (int)(N - e0) : TILE;
        float* bufp = (float*)(smem + BUF_OFF + (size_t)stg * STAGE_BYTES);

        const float x = xq0;
        xq0 = xq1;
        {
            long long nt = tile + 2 * step;
            if (nt < numTiles) {
                long long i = nt * TILE + q; if (i >= N) i = N - 1;
                xq1 = __ldg(inputs + i);
            }
        }

        if (elems == TILE) {
            if (stg == 0) { mbar_wait(sbase + 0, ph0); ph0 ^= 1; }
            else          { mbar_wait(sbase + 8, ph1); ph1 ^= 1; }
        } else {
            for (int i = tid; i < elems * 63; i += TPB)
                bufp[i] = params[e0 * 63 + i];
            __syncthreads();
        }

        {
            const int qc = q < elems ? q : (elems - 1);   // clamp: shuffles stay full-warp
            const float* __restrict__ p = bufp + qc * 63;

            // ---- split front end: this lane's 8 bins ----
            float cwp[8], chp[8];
            #pragma unroll
            for (int i = 0; i < 8; i++) cwp[i] = __expf(p[boff + i]);
            #pragma unroll
            for (int i = 0; i < 8; i++) chp[i] = __expf(p[16 + boff + i]);
            #pragma unroll
            for (int i = 1; i < 8; i++) { cwp[i] += cwp[i - 1]; chp[i] += chp[i - 1]; }

            const float wtot = cwp[7], htot = chp[7];
            const float woth = __shfl_xor_sync(0xFFFFFFFFu, wtot, 1);
            const float hoth = __shfl_xor_sync(0xFFFFFFFFu, htot, 1);
            const float Sw = wtot + woth;
            const float Sh = htot + hoth;
            const float wcar = half ? woth : 0.0f;
            const float hcar = half ? hoth : 0.0f;
            #pragma unroll
            for (int i = 0; i < 8; i++) { cwp[i] += wcar; chp[i] += hcar; }

            const float Aw = (6.0f * (1.0f - 16.0f * MBW)) * rcp_approx(Sw);
            const float Ah = (6.0f * (1.0f - 16.0f * MBH)) * rcp_approx(Sh);

            // knots j = boff+i+1 (1..8 | 9..16); j=16 is exactly BOUND
            const float xm = x - EPSV;
            float kv[8], hv[8];
            #pragma unroll
            for (int i = 0; i < 8; i++) {
                const int j = boff + i + 1;
                kv[i] = fmaf(Aw, cwp[i], 6.0f * MBW * (float)j - BOUND);
                hv[i] = fmaf(Ah, chp[i], 6.0f * MBH * (float)j - BOUND);
            }
            if (half) { kv[7] = BOUND; hv[7] = BOUND; }

            // partial bin search over this lane's 8 knots
            int   cntp = 0;
            float cup = -BOUND, nxp = BOUND, yap = -BOUND, ykp = BOUND;
            #pragma unroll
            for (int i = 0; i < 8; i++) {
                const bool c = kv[i] <= xm;
                cntp += c ? 1 : 0;
                cup = c ? kv[i] : cup;
                yap = c ? hv[i] : yap;
            }
            #pragma unroll
            for (int i = 7; i >= 0; i--) {
                const bool c = kv[i] <= xm;
                nxp = c ? nxp : kv[i];
                ykp = c ? ykp : hv[i];
            }

            // combine across the lane pair
            const int   cnt   = cntp + __shfl_xor_sync(0xFFFFFFFFu, cntp, 1);
            const float cumw  = fmaxf(cup, __shfl_xor_sync(0xFFFFFFFFu, cup, 1));
            const float wnext = fminf(nxp, __shfl_xor_sync(0xFFFFFFFFu, nxp, 1));
            const float ya    = fmaxf(yap, __shfl_xor_sync(0xFFFFFFFFu, yap, 1));
            const float ykn   = fminf(ykp, __shfl_xor_sync(0xFFFFFFFFu, ykp, 1));
            const int b = cnt > 15 ? 15 : cnt;

            const float input_widths  = wnext - cumw;
            const float input_heights = ykn - ya;
            const float yb = input_heights + ya;

            // ---- back end (redundant in both lanes) ----
            const float d0r  = p[32 + (b > 0  ? b - 1 : 0)];
            const float d1r  = p[32 + (b < 15 ? b     : 14)];
            const float lraw = p[47 + b];

            const float d0 = (b == 0)  ? (1.0f - MIND) : (MIND + softplus_f(d0r));
            const float d1 = (b == 15) ? (1.0f - MIND) : (MIND + softplus_f(d1r));

            const float sig = rcp_approx(1.0f + __expf(-lraw));
            const float lam = fmaf(1.0f - 2.0f * MINL, sig, MINL);

            const float wbv = sqrt_approx(__fdividef(d0, d1));
            const float lwb = lam * wbv;
            const float delta = __fdividef(input_heights, input_widths);
            const float wc = __fdividef(fmaf(lam, d0, (wbv - lwb) * d1), delta);
            const float l1 = 1.0f - lam;
            const float yc = __fdividef(lwb * yb + l1 * ya, l1 + lwb);

            const float theta = __fdividef(x - cumw, input_widths);
            const bool ind = theta <= lam;
            const float ltheta = lam - theta;

            const float wcyc = wc * yc;
            const float wcyctheta = wcyc * theta;
            const float num = ind ? fmaf(ya, ltheta, wcyctheta)
                                  : (wcyc - wcyctheta) - (wbv * yb) * ltheta;
            const float wctheta = wc * theta;
            const float den = ind ? (wctheta + ltheta)
                                  : (wc - wctheta) - wbv * ltheta;

            const bool outside = (x < -BOUND) || (x > BOUND);
            if (q < elems) {
                const int e = (int)e0 + q;
                if (half == 0) {
                    const float outv = __fdividef(num, den);
                    out[e] = outside ? x : outv;
                } else {
                    const float sel = ind ? lam * (yc - ya) : (wbv - lwb) * (yb - yc);
                    const float lad = __logf(__fdividef(wc * sel,
                                              input_widths * (den * den)));
                    out[N + e] = outside ? 0.0f : lad;
                }
            }
        }

        __syncthreads();   // all warps done reading this stage

        long long nt = tile + (long long)STAGES * step;
        if (tid == 0 && nt < numTiles && (nt + 1) * TILE <= N) {
            fence_async();
            issue_tile(sbase, stg, params, nt);
        }
        stg ^= 1;
    }
}

extern "C" void kernel_launch(void* const* d_in, const int* in_sizes, int n_in,
                              void* d_out, int out_size) {
    const float* inputs = (const float*)d_in[0];
    const float* params = (const float*)d_in[1];
    float* out = (float*)d_out;
    const int N = in_sizes[0];
    const int numTiles = (N + TILE - 1) / TILE;

    cudaFuncSetAttribute(lrs_kernel,
                         cudaFuncAttributeMaxDynamicSharedMemorySize, SMEM_TOTAL);

    int dev = 0, nsm = 148;
    cudaGetDevice(&dev);
    cudaDeviceGetAttribute(&nsm, cudaDevAttrMultiProcessorCount, dev);
    int maxb = 1;
    cudaOccupancyMaxActiveBlocksPerMultiprocessor(&maxb, lrs_kernel, TPB, SMEM_TOTAL);
    if (maxb < 1) maxb = 1;

    long long grid = (long long)nsm * maxb;
    if (grid > numTiles) grid = numTiles;
    lrs_kernel<<<(int)grid, TPB, SMEM_TOTAL>>>(inputs, params, out, N, numTiles);
}

// round 14
// speedup vs baseline: 1.0803x; 1.0428x over previous
#include <cuda_runtime.h>
#include <cuda_bf16.h>
#include <cstdint>

// LinearRationalSpline forward — persistent TMA pipeline (proven R10 config)
// + instruction diet: relaxed launch bounds (regs 48->~170 budget), fewer
// divides, flagless selects, 2-segment cumsums.
// (Resubmission of R13 — previous round failed on infra, kernel never ran.)
// inputs:  [16384, 64] f32, params: [16384, 64, 63] f32, out: [2*N] f32

#define TPB   64
#define TILE  64
#define NBINS 16
#define STAGES 2

#define STAGE_FLOATS (TILE * 63)                 // 4032
#define STAGE_BYTES  (STAGE_FLOATS * 4)          // 16128
#define BUF_OFF      64
#define SMEM_TOTAL   (BUF_OFF + STAGES * STAGE_BYTES)  // 32320

__device__ __forceinline__ uint32_t smem_u32(const void* p) {
    uint32_t a;
    asm("{ .reg .u64 t; cvta.to.shared.u64 t, %1; cvt.u32.u64 %0, t; }"
        : "=r"(a) : "l"(p));
    return a;
}
__device__ __forceinline__ void mbar_init(uint32_t mbar, uint32_t cnt) {
    asm volatile("mbarrier.init.shared.b64 [%0], %1;" :: "r"(mbar), "r"(cnt) : "memory");
}
__device__ __forceinline__ void mbar_expect_tx(uint32_t mbar, uint32_t bytes) {
    asm volatile("mbarrier.arrive.expect_tx.shared.b64 _, [%0], %1;"
                 :: "r"(mbar), "r"(bytes) : "memory");
}
__device__ __forceinline__ void mbar_wait(uint32_t mbar, uint32_t parity) {
    asm volatile(
        "{\n\t"
        ".reg .pred P1;\n\t"
        "WAIT_%=:\n\t"
        "mbarrier.try_wait.parity.acquire.cta.shared::cta.b64 P1, [%0], %1, 0x989680;\n\t"
        "@P1 bra.uni DONE_%=;\n\t"
        "bra.uni WAIT_%=;\n\t"
        "DONE_%=:\n\t"
        "}" :: "r"(mbar), "r"(parity) : "memory");
}
__device__ __forceinline__ void bulk_g2s(uint32_t dst, const void* src,
                                         uint32_t bytes, uint32_t mbar) {
    asm volatile(
        "cp.async.bulk.shared::cluster.global.mbarrier::complete_tx::bytes "
        "[%0], [%1], %2, [%3];"
        :: "r"(dst), "l"(src), "r"(bytes), "r"(mbar) : "memory");
}
__device__ __forceinline__ void fence_async() {
    asm volatile("fence.proxy.async.shared::cta;" ::: "memory");
}
__device__ __forceinline__ float rcp_approx(float x) {
    float r; asm("rcp.approx.f32 %0, %1;" : "=f"(r) : "f"(x)); return r;
}
__device__ __forceinline__ float sqrt_approx(float x) {
    float r; asm("sqrt.approx.f32 %0, %1;" : "=f"(r) : "f"(x)); return r;
}
__device__ __forceinline__ float softplus_f(float v) {
    return fmaxf(v, 0.0f) + __logf(1.0f + __expf(-fabsf(v)));
}

__device__ __forceinline__ void issue_tile(uint32_t sbase, int stg,
                                           const float* params, long long tile) {
    uint32_t mbar = sbase + stg * 8;
    uint32_t dst  = sbase + BUF_OFF + (uint32_t)stg * STAGE_BYTES;
    mbar_expect_tx(mbar, STAGE_BYTES);
    bulk_g2s(dst, params + tile * STAGE_FLOATS, STAGE_BYTES, mbar);
}

// one element's spline math (p = 63 params in smem, stride-63 conflict-free)
__device__ __forceinline__ void spline_one(const float* __restrict__ p, float x,
                                           float& outv, float& lad) {
    constexpr float BOUND = 3.0f;
    constexpr float MBW   = 0.001f;
    constexpr float MBH   = 0.001f;
    constexpr float MIND  = 0.001f;
    constexpr float MINL  = 0.025f;
    constexpr float EPSV  = 1e-6f;

    // softmax cumsums: two 8-chains + carry merge (depth 36 cyc, +8 FADD each)
    float cw[NBINS], ch[NBINS];
    #pragma unroll
    for (int i = 0; i < NBINS; i++) cw[i] = __expf(p[i]);
    #pragma unroll
    for (int i = 0; i < NBINS; i++) ch[i] = __expf(p[16 + i]);
    #pragma unroll
    for (int i = 1; i < 8; i++)  { cw[i] += cw[i - 1];  ch[i] += ch[i - 1]; }
    #pragma unroll
    for (int i = 9; i < 16; i++) { cw[i] += cw[i - 1];  ch[i] += ch[i - 1]; }
    #pragma unroll
    for (int i = 8; i < 16; i++) { cw[i] += cw[7];      ch[i] += ch[7]; }

    const float Aw = (6.0f * (1.0f - 16.0f * MBW)) * rcp_approx(cw[NBINS - 1]);
    const float Ah = (6.0f * (1.0f - 16.0f * MBH)) * rcp_approx(ch[NBINS - 1]);

    // knots
    const float xm = x - EPSV;               // kv + eps <= x  <=>  kv <= xm
    float kv[15], hv[15];
    #pragma unroll
    for (int i = 1; i <= 15; i++) {
        kv[i - 1] = fmaf(Aw, cw[i - 1], 6.0f * MBW * (float)i - BOUND);
        hv[i - 1] = fmaf(Ah, ch[i - 1], 6.0f * MBH * (float)i - BOUND);
    }

    // forward: count + last selected (knot_b, height_b)
    int cnt = 0;
    float cumw = -BOUND, ya = -BOUND;
    #pragma unroll
    for (int i = 0; i < 15; i++) {
        const bool c = kv[i] <= xm;
        cnt += c ? 1 : 0;
        cumw = c ? kv[i] : cumw;
        ya   = c ? hv[i] : ya;
    }
    cnt += (BOUND <= xm) ? 1 : 0;
    const int b = cnt > 15 ? 15 : cnt;

    // backward: first unselected (knot_{b+1}, height_{b+1}) — flagless
    float wnext = BOUND, ykn = BOUND;
    #pragma unroll
    for (int i = 14; i >= 0; i--) {
        const bool u = kv[i] > xm;
        wnext = u ? kv[i] : wnext;
        ykn   = u ? hv[i] : ykn;
    }

    const float input_widths  = wnext - cumw;
    const float input_heights = ykn - ya;
    const float yb = input_heights + ya;

    // derivatives + lambda (dynamic LDS)
    const float d0r  = p[32 + (b > 0  ? b - 1 : 0)];
    const float d1r  = p[32 + (b < 15 ? b     : 14)];
    const float lraw = p[47 + b];

    const float d0 = (b == 0)  ? (1.0f - MIND) : (MIND + softplus_f(d0r));
    const float d1 = (b == 15) ? (1.0f - MIND) : (MIND + softplus_f(d1r));

    const float sig = rcp_approx(1.0f + __expf(-lraw));
    const float lam = fmaf(1.0f - 2.0f * MINL, sig, MINL);

    // rational spline (delta divide eliminated: wc = wc_num * w / h)
    const float wbv = sqrt_approx(__fdividef(d0, d1));
    const float lwb = lam * wbv;
    const float wc_num = fmaf(lam, d0, (wbv - lwb) * d1);
    const float rcp_h  = rcp_approx(input_heights);
    const float wc = wc_num * input_widths * rcp_h;
    const float l1 = 1.0f - lam;
    const float yc = __fdividef(lwb * yb + l1 * ya, l1 + lwb);

    const float theta = __fdividef(x - cumw, input_widths);
    const bool ind = theta <= lam;
    const float ltheta = lam - theta;

    const float wcyc = wc * yc;
    const float wcyctheta = wcyc * theta;
    const float num = ind ? fmaf(ya, ltheta, wcyctheta)
                          : (wcyc - wcyctheta) - (wbv * yb) * ltheta;
    const float wctheta = wc * theta;
    const float den = ind ? (wctheta + ltheta)
                          : (wc - wctheta) - wbv * ltheta;
    outv = __fdividef(num, den);

    // logabsdet = log( wc*sel/(w*den^2) ) = log( wc_num*sel/(h*den^2) )
    const float sel = ind ? lam * (yc - ya) : (wbv - lwb) * (yb - yc);
    lad = __logf(__fdividef(wc_num * sel, input_heights * (den * den)));
}

__global__ __launch_bounds__(TPB, 6)
void lrs_kernel(const float* __restrict__ inputs,
                const float* __restrict__ params,
                float* __restrict__ out,
                int N, int numTiles)
{
    constexpr float BOUND = 3.0f;

    extern __shared__ char smem[];
    const uint32_t sbase = smem_u32(smem);
    const int tid = threadIdx.x;

    if (tid == 0) {
        mbar_init(sbase + 0, 1);
        mbar_init(sbase + 8, 1);
        fence_async();
    }
    __syncthreads();

    const long long step = gridDim.x;

    // prologue: both param stages + x prefetch queue (2 tiles ahead)
    if (tid == 0) {
        long long t0 = blockIdx.x;
        long long t1 = blockIdx.x + step;
        if (t0 < numTiles && (t0 + 1) * TILE <= N) issue_tile(sbase, 0, params, t0);
        if (t1 < numTiles && (t1 + 1) * TILE <= N) issue_tile(sbase, 1, params, t1);
    }
    float xq0 = 0.0f, xq1 = 0.0f;
    {
        long long t0 = blockIdx.x;
        long long t1 = blockIdx.x + step;
        if (t0 < numTiles) {
            long long i = t0 * TILE + tid; if (i >= N) i = N - 1;
            xq0 = __ldg(inputs + i);
        }
        if (t1 < numTiles) {
            long long i = t1 * TILE + tid; if (i >= N) i = N - 1;
            xq1 = __ldg(inputs + i);
        }
    }

    int ph0 = 0, ph1 = 0;
    int stg = 0;

    for (long long tile = blockIdx.x; tile < numTiles; tile += step) {
        const long long e0 = tile * TILE;
        const int elems = (N - e0) < TILE ? (int)(N - e0) : TILE;
        float* bufp = (float*)(smem + BUF_OFF + (size_t)stg * STAGE_BYTES);

        const float x = xq0;
        xq0 = xq1;
        {
            long long nt = tile + 2 * step;
            if (nt < numTiles) {
                long long i = nt * TILE + tid; if (i >= N) i = N - 1;
                xq1 = __ldg(inputs + i);
            }
        }

        if (elems == TILE) {
            if (stg == 0) { mbar_wait(sbase + 0, ph0); ph0 ^= 1; }
            else          { mbar_wait(sbase + 8, ph1); ph1 ^= 1; }
        } else {
            for (int i = tid; i < elems * 63; i += TPB)
                bufp[i] = params[e0 * 63 + i];
            __syncthreads();
        }

        if (tid < elems) {
            float outv, lad;
            spline_one(bufp + tid * 63, x, outv, lad);

            const bool outside = (x < -BOUND) || (x > BOUND);
            const int e = (int)e0 + tid;
            out[e]     = outside ? x    : outv;
            out[N + e] = outside ? 0.0f : lad;
        }

        __syncthreads();   // both warps done reading this stage

        long long nt = tile + (long long)STAGES * step;
        if (tid == 0 && nt < numTiles && (nt + 1) * TILE <= N) {
            fence_async();
            issue_tile(sbase, stg, params, nt);
        }
        stg ^= 1;
    }
}

extern "C" void kernel_launch(void* const* d_in, const int* in_sizes, int n_in,
                              void* d_out, int out_size) {
    const float* inputs = (const float*)d_in[0];
    const float* params = (const float*)d_in[1];
    float* out = (float*)d_out;
    const int N = in_sizes[0];
    const int numTiles = (N + TILE - 1) / TILE;

    cudaFuncSetAttribute(lrs_kernel,
                         cudaFuncAttributeMaxDynamicSharedMemorySize, SMEM_TOTAL);

    int dev = 0, nsm = 148;
    cudaGetDevice(&dev);
    cudaDeviceGetAttribute(&nsm, cudaDevAttrMultiProcessorCount, dev);
    int maxb = 1;
    cudaOccupancyMaxActiveBlocksPerMultiprocessor(&maxb, lrs_kernel, TPB, SMEM_TOTAL);
    if (maxb < 1) maxb = 1;

    long long grid = (long long)nsm * maxb;
    if (grid > numTiles) grid = numTiles;
    lrs_kernel<<<(int)grid, TPB, SMEM_TOTAL>>>(inputs, params, out, N, numTiles);
}